// round 15
// baseline (speedup 1.0000x reference)
#include <cuda_runtime.h>
#include <cuda_bf16.h>
#include <math.h>
#include <stdint.h>

// Problem dims
#define BB 8
#define HH 256
#define WW 256
#define CC 256
#define MROWS (BB*HH*WW)        // 524288 pixel rows
#define NBH   (BB*HH)           // 2048 attention slices

typedef unsigned long long u64;

// ---------------- device scratch (allocation rules: __device__ globals) ------
__device__ __nv_bfloat162 g_xhi[(size_t)MROWS * CC / 2];
__device__ __nv_bfloat162 g_xlo[(size_t)MROWS * CC / 2];
// t = x * (Wq Wk^T) as bf16 hi/lo; v = x*Wv + bv as bf16 hi
__device__ __nv_bfloat16 g_th[(size_t)MROWS * CC];
__device__ __nv_bfloat16 g_tl[(size_t)MROWS * CC];
__device__ __nv_bfloat16 g_vh[(size_t)MROWS * CC];
// M^T = (Wq Wk^T)^T in [n][k] layout, bf16 hi/lo; Wv^T hi
__device__ __nv_bfloat16 g_mthi[CC * CC];
__device__ __nv_bfloat16 g_mtlo[CC * CC];
__device__ __nv_bfloat16 g_wvth[CC * CC];
__device__ float g_u[CC];              // Wk * bq
__device__ float g_c[MROWS];           // c_j = x_j . u  (softmax column bias)

// ---------------- warp-mma + cp.async helpers (baseline PTX) -----------------
__device__ __forceinline__ uint32_t smem_to_u32(const void* p) {
    uint32_t a;
    asm("{ .reg .u64 t; cvta.to.shared.u64 t, %1; cvt.u32.u64 %0, t; }"
        : "=r"(a) : "l"(p));
    return a;
}
__device__ __forceinline__ void ldm4(uint32_t* r, uint32_t addr) {
    asm volatile("ldmatrix.sync.aligned.m8n8.x4.shared.b16 {%0,%1,%2,%3}, [%4];"
                 : "=r"(r[0]), "=r"(r[1]), "=r"(r[2]), "=r"(r[3]) : "r"(addr));
}
__device__ __forceinline__ void ldm4t(uint32_t* r, uint32_t addr) {
    asm volatile("ldmatrix.sync.aligned.m8n8.x4.trans.shared.b16 {%0,%1,%2,%3}, [%4];"
                 : "=r"(r[0]), "=r"(r[1]), "=r"(r[2]), "=r"(r[3]) : "r"(addr));
}
__device__ __forceinline__ void mma16816(float* c, const uint32_t* a, const uint32_t* b) {
    asm volatile("mma.sync.aligned.m16n8k16.row.col.f32.bf16.bf16.f32 "
                 "{%0,%1,%2,%3}, {%4,%5,%6,%7}, {%8,%9}, {%0,%1,%2,%3};"
                 : "+f"(c[0]), "+f"(c[1]), "+f"(c[2]), "+f"(c[3])
                 : "r"(a[0]), "r"(a[1]), "r"(a[2]), "r"(a[3]),
                   "r"(b[0]), "r"(b[1]));
}
__device__ __forceinline__ uint32_t pk(float lo, float hi) {
    uint32_t r;
    asm("cvt.rn.bf16x2.f32 %0, %1, %2;" : "=r"(r) : "f"(hi), "f"(lo));
    return r;
}
__device__ __forceinline__ void cpa16(uint32_t s, const void* g) {
    asm volatile("cp.async.cg.shared.global [%0], [%1], 16;"
                 :: "r"(s), "l"(__cvta_generic_to_global(g)));
}
#define CP_COMMIT() asm volatile("cp.async.commit_group;" ::: "memory")
#define CP_WAIT0()  asm volatile("cp.async.wait_group 0;" ::: "memory")
#define CP_WAIT1()  asm volatile("cp.async.wait_group 1;" ::: "memory")

// ---------------------------------------------------------------------------
// prep: M^T[c'][c] = sum_d Wq[c,d]*Wk[c',d]  (fp32, split hi/lo), u = Wk*bq
// ---------------------------------------------------------------------------
__global__ __launch_bounds__(256)
void prep_kernel(const float* __restrict__ wq,
                 const float* __restrict__ wk,
                 const float* __restrict__ bq)
{
    __shared__ float wkrow[CC];
    __shared__ float bqs[CC];
    const int cp = blockIdx.x;       // c'
    const int c  = threadIdx.x;      // c
    wkrow[c] = wk[cp * CC + c];      // Wk row c' (coalesced)
    bqs[c]   = bq[c];
    __syncthreads();

    float s = 0.f;
#pragma unroll 8
    for (int d = 0; d < CC; d++)
        s += wq[c * CC + d] * wkrow[d];
    __nv_bfloat16 h = __float2bfloat16(s);
    __nv_bfloat16 l = __float2bfloat16(s - __bfloat162float(h));
    g_mthi[cp * CC + c] = h;
    g_mtlo[cp * CC + c] = l;

    if (cp == 0) {   // u[c] = sum_d Wk[c,d]*bq[d]
        float uu = 0.f;
#pragma unroll 8
        for (int d = 0; d < CC; d++)
            uu += wk[c * CC + d] * bqs[d];
        g_u[c] = uu;
    }
}

// Wv^T hi  (v projection uses hi.hi only)
__global__ __launch_bounds__(256)
void cvt_wv_kernel(const float* __restrict__ wv)
{
    int k = blockIdx.x;          // 0..255
    int n = threadIdx.x;         // 0..255
    g_wvth[n * CC + k] = __float2bfloat16(wv[k * CC + n]);
}

// ---------------------------------------------------------------------------
// cvt_x: x -> bf16 hi/lo, plus c_i = x_i . u  (block = 4 rows of 256)
// ---------------------------------------------------------------------------
__global__ __launch_bounds__(256)
void cvt_x_kernel(const float* __restrict__ x)
{
    __shared__ float red[8];
    const int tid = threadIdx.x;
    size_t i = (size_t)blockIdx.x * 256 + tid;   // float4 index
    float4 v = ((const float4*)x)[i];
    __nv_bfloat16 h0 = __float2bfloat16(v.x);
    __nv_bfloat16 h1 = __float2bfloat16(v.y);
    __nv_bfloat16 h2 = __float2bfloat16(v.z);
    __nv_bfloat16 h3 = __float2bfloat16(v.w);
    __nv_bfloat16 l0 = __float2bfloat16(v.x - __bfloat162float(h0));
    __nv_bfloat16 l1 = __float2bfloat16(v.y - __bfloat162float(h1));
    __nv_bfloat16 l2 = __float2bfloat16(v.z - __bfloat162float(h2));
    __nv_bfloat16 l3 = __float2bfloat16(v.w - __bfloat162float(h3));
    g_xhi[i * 2 + 0] = __halves2bfloat162(h0, h1);
    g_xhi[i * 2 + 1] = __halves2bfloat162(h2, h3);
    g_xlo[i * 2 + 0] = __halves2bfloat162(l0, l1);
    g_xlo[i * 2 + 1] = __halves2bfloat162(l2, l3);

    // c_i = x_i . u  : 64 threads (2 warps) per row
    int col = (tid * 4) & 255;
    float p = v.x * g_u[col] + v.y * g_u[col + 1]
            + v.z * g_u[col + 2] + v.w * g_u[col + 3];
#pragma unroll
    for (int o = 16; o > 0; o >>= 1)
        p += __shfl_xor_sync(0xffffffffu, p, o);
    if ((tid & 31) == 0) red[tid >> 5] = p;
    __syncthreads();
    if (tid < 4)
        g_c[(size_t)blockIdx.x * 4 + tid] = red[2 * tid] + red[2 * tid + 1];
}

// ---------------------------------------------------------------------------
// t/v GEMM via warp-level mma.sync.
// sel 0: t = x * M      (bf16x3), store hi/lo.  sel 1: v = x*Wv + bv (hi only)
// CTA: M=128 x N=128, 8 warps (4 m x 2 n), warp tile 32x64.
// Grid (4, MROWS/128): the 4 (nb,sel) CTAs sharing an A-tile are launch-
// adjacent -> same wave -> A tile read once from DRAM, then L2.
// ---------------------------------------------------------------------------
#define KSTR 72
#define ASZ  (128 * KSTR)              // bf16 elements per tile
#define SM_AH 0
#define SM_AL (ASZ)
#define SM_BH (2 * ASZ)
#define SM_BL (3 * ASZ)
#define QKV_SMEM (4 * ASZ * 2)         // 73728 bytes

__global__ __launch_bounds__(256, 2)
void tv_mma_kernel(const float* __restrict__ bv)
{
    extern __shared__ __align__(128) __nv_bfloat16 smem[];
    const uint32_t sb = smem_to_u32(smem);

    const int tid  = threadIdx.x;
    const int wid  = tid >> 5;
    const int lane = tid & 31;
    const int wm   = wid & 3;          // 0..3  (m)
    const int wn   = wid >> 2;         // 0..1  (n)

    const int m0  = blockIdx.y * 128;
    const int nb  = (blockIdx.x & 1) * 128;
    const int sel = blockIdx.x >> 1;   // 0 = t, 1 = v
    const bool full = (sel == 0);
    __nv_bfloat16* oh = full ? g_th : g_vh;
    __nv_bfloat16* ol = g_tl;
    const __nv_bfloat16* __restrict__ wh = full ? g_mthi : g_wvth;
    const __nv_bfloat16* __restrict__ wl = g_mtlo;
    const __nv_bfloat16* __restrict__ xh = (const __nv_bfloat16*)g_xhi;
    const __nv_bfloat16* __restrict__ xl = (const __nv_bfloat16*)g_xlo;

    float acc[2][8][4];
#pragma unroll
    for (int mt = 0; mt < 2; mt++)
#pragma unroll
        for (int nt = 0; nt < 8; nt++)
#pragma unroll
            for (int j = 0; j < 4; j++) acc[mt][nt][j] = 0.f;

    const int q  = lane >> 3;          // matrix index 0..3
    const int ri = lane & 7;           // row within matrix
    const uint32_t a_row = (uint32_t)((wm * 32 + (q & 1) * 8 + ri) * (KSTR * 2) + (q >> 1) * 16);
    const uint32_t b_row = (uint32_t)((wn * 64 + (q >> 1) * 8 + ri) * (KSTR * 2) + (q & 1) * 16);

    for (int ct = 0; ct < 4; ct++) {
        const int kt = ct * 64;
        __syncthreads();
#pragma unroll
        for (int it = 0; it < 4; it++) {
            int u = tid + it * 256;            // 0..1023
            int r = u >> 3, c = u & 7;
            size_t src = (size_t)(m0 + r) * CC + kt + c * 8;
            uint32_t d = (uint32_t)((r * KSTR + c * 8) * 2);
            cpa16(sb + SM_AH * 2 + d, xh + src);
            if (full) cpa16(sb + SM_AL * 2 + d, xl + src);
        }
#pragma unroll
        for (int it = 0; it < 4; it++) {
            int u = tid + it * 256;
            int r = u >> 3, c = u & 7;
            size_t src = (size_t)(nb + r) * CC + kt + c * 8;
            uint32_t d = (uint32_t)((r * KSTR + c * 8) * 2);
            cpa16(sb + SM_BH * 2 + d, wh + src);
            if (full) cpa16(sb + SM_BL * 2 + d, wl + src);
        }
        CP_COMMIT();
        CP_WAIT0();
        __syncthreads();

#pragma unroll
        for (int ks = 0; ks < 4; ks++) {
            const uint32_t koff = (uint32_t)(ks * 32);
            uint32_t ah[2][4], ax[2][4], bh[4][4], bx[4][4];
#pragma unroll
            for (int mt = 0; mt < 2; mt++)
                ldm4(ah[mt], sb + SM_AH * 2 + a_row + (uint32_t)(mt * 16 * KSTR * 2) + koff);
#pragma unroll
            for (int np = 0; np < 4; np++)
                ldm4(bh[np], sb + SM_BH * 2 + b_row + (uint32_t)(np * 16 * KSTR * 2) + koff);
#pragma unroll
            for (int mt = 0; mt < 2; mt++)
#pragma unroll
                for (int nt = 0; nt < 8; nt++)
                    mma16816(acc[mt][nt], ah[mt], &bh[nt >> 1][(nt & 1) * 2]);
            if (full) {
#pragma unroll
                for (int np = 0; np < 4; np++)
                    ldm4(bx[np], sb + SM_BL * 2 + b_row + (uint32_t)(np * 16 * KSTR * 2) + koff);
#pragma unroll
                for (int mt = 0; mt < 2; mt++)
#pragma unroll
                    for (int nt = 0; nt < 8; nt++)
                        mma16816(acc[mt][nt], ah[mt], &bx[nt >> 1][(nt & 1) * 2]);
#pragma unroll
                for (int mt = 0; mt < 2; mt++)
                    ldm4(ax[mt], sb + SM_AL * 2 + a_row + (uint32_t)(mt * 16 * KSTR * 2) + koff);
#pragma unroll
                for (int mt = 0; mt < 2; mt++)
#pragma unroll
                    for (int nt = 0; nt < 8; nt++)
                        mma16816(acc[mt][nt], ax[mt], &bh[nt >> 1][(nt & 1) * 2]);
            }
        }
    }

    // epilogue
    const int g = lane >> 2;
    const int t = lane & 3;
#pragma unroll
    for (int mt = 0; mt < 2; mt++) {
        int row = m0 + wm * 32 + mt * 16 + g;
#pragma unroll
        for (int nt = 0; nt < 8; nt++) {
            int col = nb + wn * 64 + nt * 8 + 2 * t;
            float2 bb = full ? make_float2(0.f, 0.f) : *(const float2*)&bv[col];
#pragma unroll
            for (int h = 0; h < 2; h++) {
                float a = acc[mt][nt][2 * h]     + bb.x;
                float b = acc[mt][nt][2 * h + 1] + bb.y;
                size_t off = (size_t)(row + 8 * h) * CC + col;
                __nv_bfloat16 ha = __float2bfloat16(a);
                __nv_bfloat16 hb = __float2bfloat16(b);
                *(__nv_bfloat162*)&oh[off] = __halves2bfloat162(ha, hb);
                if (full) {
                    __nv_bfloat16 la = __float2bfloat16(a - __bfloat162float(ha));
                    __nv_bfloat16 lb = __float2bfloat16(b - __bfloat162float(hb));
                    *(__nv_bfloat162*)&ol[off] = __halves2bfloat162(la, lb);
                }
            }
        }
    }
}

// ---------------------------------------------------------------------------
// Attention via mma.sync per (b,h) slice, flash-style register softmax.
// S = t x^T (bf16x3) + c_j; softmax via quad shfl; P from S fragments;
// O = P * V_hi, V double-buffered; residual x re-read as bf16 hi/lo from L2
// into the freed Q smem area (overlapped with PV) instead of fp32 from DRAM.
// ---------------------------------------------------------------------------
#define AT_STR 264                      // bf16 row stride (528B: conflict-free)
#define QH_E 0
#define QL_E 33792                      // 128*264
#define T0_E 67584                      // K hi  / V buf0  (64*264 elts)
#define T1_E 84480                      // K lo  / V buf1
#define AT_SMEM ((T1_E + 64 * AT_STR) * 2)   // 202752 bytes
#define AT_SMEM_TOT (AT_SMEM + 1024)         // + c_j slice (256 floats)

__global__ __launch_bounds__(256, 1)
void attn_mma_kernel(const float* __restrict__ gamma,
                     float* __restrict__ out)
{
    extern __shared__ __align__(128) __nv_bfloat16 sm[];
    const uint32_t sb = smem_to_u32(sm);
    float* csm = (float*)((char*)sm + AT_SMEM);

    const int bh = blockIdx.x;
    const size_t base = (size_t)bh * WW * CC;
    const int tid  = threadIdx.x;
    const int wid  = tid >> 5;
    const int lane = tid & 31;
    const int g  = lane >> 2, t  = lane & 3;
    const int qm = lane >> 3, ri = lane & 7;

    csm[tid] = g_c[(size_t)bh * WW + tid];   // softmax column bias slice

    // ldmatrix per-lane addresses
    const uint32_t a_hi = sb +
        (uint32_t)(((wid * 16 + (qm & 1) * 8 + ri) * AT_STR + (qm >> 1) * 8) * 2);
    const uint32_t a_lo = a_hi + QL_E * 2;
    const uint32_t bk_off = (uint32_t)((((qm >> 1) * 8 + ri) * AT_STR + (qm & 1) * 8) * 2);
    const uint32_t bv_off = (uint32_t)((((qm & 1) * 8 + ri) * AT_STR + (qm >> 1) * 8) * 2);
    const uint32_t buf0 = sb + T0_E * 2;
    const uint32_t buf1 = sb + T1_E * 2;

    for (int qb = 0; qb < 2; qb++) {
        __syncthreads();   // previous iteration fully done with smem

        // ---- async-load T block hi/lo (128 x 256) : Q-role ----
        {
            const __nv_bfloat16* qh = g_th + base + (size_t)qb * 128 * CC;
            const __nv_bfloat16* ql = g_tl + base + (size_t)qb * 128 * CC;
#pragma unroll
            for (int it = 0; it < 16; it++) {
                int u = tid + it * 256;
                int r = u >> 5, c8 = u & 31;
                uint32_t d = (uint32_t)((r * AT_STR + c8 * 8) * 2);
                cpa16(sb + QH_E * 2 + d, qh + r * CC + c8 * 8);
                cpa16(sb + QL_E * 2 + d, ql + r * CC + c8 * 8);
            }
            CP_COMMIT();
        }
        // ---- async-load x tile 0 (hi->buf0, lo->buf1) : K-role ----
        {
            const __nv_bfloat16* kh = (const __nv_bfloat16*)g_xhi + base;
            const __nv_bfloat16* kl = (const __nv_bfloat16*)g_xlo + base;
#pragma unroll
            for (int it = 0; it < 8; it++) {
                int u = tid + it * 256;
                int r = u >> 5, c8 = u & 31;
                uint32_t d = (uint32_t)((r * AT_STR + c8 * 8) * 2);
                cpa16(buf0 + d, kh + r * CC + c8 * 8);
                cpa16(buf1 + d, kl + r * CC + c8 * 8);
            }
            CP_COMMIT();
        }

        // ---- S = T x^T (per warp: 16 rows x 256 keys), bf16x3 ----
        float sacc[32][4];
#pragma unroll
        for (int nt = 0; nt < 32; nt++)
#pragma unroll
            for (int j = 0; j < 4; j++) sacc[nt][j] = 0.f;

        for (int kt = 0; kt < 4; kt++) {
            CP_WAIT0();
            __syncthreads();

#pragma unroll 2
            for (int kc = 0; kc < 16; kc++) {
                uint32_t ah[4], al[4];
                ldm4(ah, a_hi + kc * 32);
                ldm4(al, a_lo + kc * 32);
#pragma unroll
                for (int jg = 0; jg < 4; jg++) {
                    uint32_t bh4[4], bl4[4];
                    uint32_t roff = bk_off + (uint32_t)(jg * 16 * AT_STR * 2) + kc * 32;
                    ldm4(bh4, buf0 + roff);
                    ldm4(bl4, buf1 + roff);
                    float* s0 = sacc[kt * 8 + jg * 2];
                    float* s1 = sacc[kt * 8 + jg * 2 + 1];
                    mma16816(s0, ah, bh4 + 0); mma16816(s1, ah, bh4 + 2);
                    mma16816(s0, ah, bl4 + 0); mma16816(s1, ah, bl4 + 2);
                    mma16816(s0, al, bh4 + 0); mma16816(s1, al, bh4 + 2);
                }
            }
            __syncthreads();
            if (kt < 3) {   // stream next x tile
                const __nv_bfloat16* kh = (const __nv_bfloat16*)g_xhi + base + (size_t)(kt + 1) * 64 * CC;
                const __nv_bfloat16* kl = (const __nv_bfloat16*)g_xlo + base + (size_t)(kt + 1) * 64 * CC;
#pragma unroll
                for (int it = 0; it < 8; it++) {
                    int u = tid + it * 256;
                    int r = u >> 5, c8 = u & 31;
                    uint32_t d = (uint32_t)((r * AT_STR + c8 * 8) * 2);
                    cpa16(buf0 + d, kh + r * CC + c8 * 8);
                    cpa16(buf1 + d, kl + r * CC + c8 * 8);
                }
                CP_COMMIT();
            }
        }

        // ---- Q area free: prefetch residual x hi/lo for this qb block ----
        {
            const __nv_bfloat16* xh = (const __nv_bfloat16*)g_xhi + base + (size_t)qb * 128 * CC;
            const __nv_bfloat16* xl = (const __nv_bfloat16*)g_xlo + base + (size_t)qb * 128 * CC;
#pragma unroll
            for (int it = 0; it < 16; it++) {
                int u = tid + it * 256;
                int r = u >> 5, c8 = u & 31;
                uint32_t d = (uint32_t)((r * AT_STR + c8 * 8) * 2);
                cpa16(sb + QH_E * 2 + d, xh + r * CC + c8 * 8);
                cpa16(sb + QL_E * 2 + d, xl + r * CC + c8 * 8);
            }
            CP_COMMIT();
        }
        // ---- prefetch V tile 0 into buf0 (overlaps softmax) ----
        {
            const __nv_bfloat16* vh = g_vh + base;
#pragma unroll
            for (int it = 0; it < 8; it++) {
                int u = tid + it * 256;
                int r = u >> 5, c8 = u & 31;
                cpa16(buf0 + (uint32_t)((r * AT_STR + c8 * 8) * 2), vh + r * CC + c8 * 8);
            }
            CP_COMMIT();
        }

        // ---- add softmax column bias c_j ----
#pragma unroll
        for (int nt = 0; nt < 32; nt++) {
            float c0 = csm[nt * 8 + 2 * t];
            float c1 = csm[nt * 8 + 2 * t + 1];
            sacc[nt][0] += c0; sacc[nt][1] += c1;
            sacc[nt][2] += c0; sacc[nt][3] += c1;
        }

        // ---- softmax (warp-local; rows g and g+8 per thread-quad) ----
        float mx0 = -1e30f, mx1 = -1e30f;
#pragma unroll
        for (int nt = 0; nt < 32; nt++) {
            mx0 = fmaxf(mx0, fmaxf(sacc[nt][0], sacc[nt][1]));
            mx1 = fmaxf(mx1, fmaxf(sacc[nt][2], sacc[nt][3]));
        }
        mx0 = fmaxf(mx0, __shfl_xor_sync(0xffffffffu, mx0, 1));
        mx0 = fmaxf(mx0, __shfl_xor_sync(0xffffffffu, mx0, 2));
        mx1 = fmaxf(mx1, __shfl_xor_sync(0xffffffffu, mx1, 1));
        mx1 = fmaxf(mx1, __shfl_xor_sync(0xffffffffu, mx1, 2));
        float sm0 = 0.f, sm1 = 0.f;
#pragma unroll
        for (int nt = 0; nt < 32; nt++) {
            sacc[nt][0] = __expf(sacc[nt][0] - mx0);
            sacc[nt][1] = __expf(sacc[nt][1] - mx0);
            sacc[nt][2] = __expf(sacc[nt][2] - mx1);
            sacc[nt][3] = __expf(sacc[nt][3] - mx1);
            sm0 += sacc[nt][0] + sacc[nt][1];
            sm1 += sacc[nt][2] + sacc[nt][3];
        }
        sm0 += __shfl_xor_sync(0xffffffffu, sm0, 1);
        sm0 += __shfl_xor_sync(0xffffffffu, sm0, 2);
        sm1 += __shfl_xor_sync(0xffffffffu, sm1, 1);
        sm1 += __shfl_xor_sync(0xffffffffu, sm1, 2);
        const float inv0 = 1.f / sm0, inv1 = 1.f / sm1;

        // ---- pack P fragments straight from S accumulators ----
        uint32_t phi[16][4];
#pragma unroll
        for (int m = 0; m < 16; m++) {
            phi[m][0] = pk(sacc[2 * m][0] * inv0,     sacc[2 * m][1] * inv0);
            phi[m][1] = pk(sacc[2 * m][2] * inv1,     sacc[2 * m][3] * inv1);
            phi[m][2] = pk(sacc[2 * m + 1][0] * inv0, sacc[2 * m + 1][1] * inv0);
            phi[m][3] = pk(sacc[2 * m + 1][2] * inv1, sacc[2 * m + 1][3] * inv1);
        }

        // ---- O = P V_hi, single pass, V double-buffered ----
        float oacc[32][4];
#pragma unroll
        for (int nt = 0; nt < 32; nt++)
#pragma unroll
            for (int j = 0; j < 4; j++) oacc[nt][j] = 0.f;

        for (int vt = 0; vt < 4; vt++) {
            if (vt < 3) {   // prefetch next V tile into the other buffer
                const __nv_bfloat16* vh = g_vh + base + (size_t)(vt + 1) * 64 * CC;
                uint32_t nbuf = ((vt + 1) & 1) ? buf1 : buf0;
#pragma unroll
                for (int it = 0; it < 8; it++) {
                    int u = tid + it * 256;
                    int r = u >> 5, c8 = u & 31;
                    cpa16(nbuf + (uint32_t)((r * AT_STR + c8 * 8) * 2), vh + r * CC + c8 * 8);
                }
                CP_COMMIT();
                CP_WAIT1();
            } else {
                CP_WAIT0();
            }
            __syncthreads();

            const uint32_t cbuf = (vt & 1) ? buf1 : buf0;
#pragma unroll
            for (int ml = 0; ml < 4; ml++) {
                const uint32_t* p = phi[vt * 4 + ml];
#pragma unroll
                for (int cg = 0; cg < 16; cg++) {
                    uint32_t bh4[4];
                    ldm4t(bh4, cbuf + bv_off + (uint32_t)(ml * 16 * AT_STR * 2) + cg * 32);
                    mma16816(oacc[cg * 2],     p, bh4 + 0);
                    mma16816(oacc[cg * 2 + 1], p, bh4 + 2);
                }
            }
            __syncthreads();
        }

        // ---- epilogue: out = gamma * O + (xhi + xlo)  [residual from smem] ----
        const int r0loc = wid * 16 + g;
#pragma unroll
        for (int nt = 0; nt < 32; nt++) {
            int c = nt * 8 + 2 * t;
            float2 gm = *(const float2*)&gamma[c];
            size_t o0 = base + (size_t)(qb * 128 + r0loc) * CC + c;
            size_t o1 = o0 + (size_t)8 * CC;
            __nv_bfloat162 h0 = *(__nv_bfloat162*)&sm[QH_E + r0loc * AT_STR + c];
            __nv_bfloat162 l0 = *(__nv_bfloat162*)&sm[QL_E + r0loc * AT_STR + c];
            __nv_bfloat162 h1 = *(__nv_bfloat162*)&sm[QH_E + (r0loc + 8) * AT_STR + c];
            __nv_bfloat162 l1 = *(__nv_bfloat162*)&sm[QL_E + (r0loc + 8) * AT_STR + c];
            float2 w0, w1;
            w0.x = gm.x * oacc[nt][0] + (__bfloat162float(h0.x) + __bfloat162float(l0.x));
            w0.y = gm.y * oacc[nt][1] + (__bfloat162float(h0.y) + __bfloat162float(l0.y));
            w1.x = gm.x * oacc[nt][2] + (__bfloat162float(h1.x) + __bfloat162float(l1.x));
            w1.y = gm.y * oacc[nt][3] + (__bfloat162float(h1.y) + __bfloat162float(l1.y));
            *(float2*)&out[o0] = w0;
            *(float2*)&out[o1] = w1;
        }
    }
}

// ---------------------------------------------------------------------------
extern "C" void kernel_launch(void* const* d_in, const int* in_sizes, int n_in,
                              void* d_out, int out_size)
{
    const float* x     = (const float*)d_in[0];
    const float* wq    = (const float*)d_in[1];
    const float* bq    = (const float*)d_in[2];
    const float* wk    = (const float*)d_in[3];
    const float* wv    = (const float*)d_in[5];
    const float* bv    = (const float*)d_in[6];
    const float* gamma = (const float*)d_in[7];
    float* out = (float*)d_out;

    cudaFuncSetAttribute(tv_mma_kernel,
                         cudaFuncAttributeMaxDynamicSharedMemorySize, QKV_SMEM);
    cudaFuncSetAttribute(attn_mma_kernel,
                         cudaFuncAttributeMaxDynamicSharedMemorySize, AT_SMEM_TOT);

    // 1) M = Wq Wk^T (hi/lo), u = Wk bq ; Wv^T hi
    prep_kernel<<<CC, CC>>>(wq, wk, bq);
    cvt_wv_kernel<<<CC, CC>>>(wv);

    // 2) x -> bf16 hi/lo + c_i = x_i . u   (needs g_u from prep)
    cvt_x_kernel<<<(MROWS * CC / 4) / 256, 256>>>(x);

    // 3) t = x M (bf16x3, hi/lo out); v = x Wv + bv (hi out)
    tv_mma_kernel<<<dim3(4, MROWS / 128), 256, QKV_SMEM>>>(bv);

    // 4) attention + residual via warp-mma, cp.async pipelined
    attn_mma_kernel<<<NBH, 256, AT_SMEM_TOT>>>(gamma, out);
}

// round 16
// speedup vs baseline: 1.3981x; 1.3981x over previous
#include <cuda_runtime.h>
#include <cuda_bf16.h>
#include <math.h>
#include <stdint.h>

// Problem dims
#define BB 8
#define HH 256
#define WW 256
#define CC 256
#define MROWS (BB*HH*WW)        // 524288 pixel rows
#define NBH   (BB*HH)           // 2048 attention slices

typedef unsigned long long u64;

// ---------------- device scratch (allocation rules: __device__ globals) ------
__device__ __nv_bfloat162 g_xhi[(size_t)MROWS * CC / 2];
__device__ __nv_bfloat162 g_xlo[(size_t)MROWS * CC / 2];
// t = x * (Wq Wk^T) as bf16 hi/lo; v = x*Wv + bv as bf16 hi
__device__ __nv_bfloat16 g_th[(size_t)MROWS * CC];
__device__ __nv_bfloat16 g_tl[(size_t)MROWS * CC];
__device__ __nv_bfloat16 g_vh[(size_t)MROWS * CC];
// M^T = (Wq Wk^T)^T in [n][k] layout, bf16 hi/lo; Wv^T hi
__device__ __nv_bfloat16 g_mthi[CC * CC];
__device__ __nv_bfloat16 g_mtlo[CC * CC];
__device__ __nv_bfloat16 g_wvth[CC * CC];
__device__ float g_u[CC];              // Wk * bq
__device__ float g_c[MROWS];           // c_j = x_j . u  (softmax column bias)

// ---------------- warp-mma + cp.async helpers (baseline PTX) -----------------
__device__ __forceinline__ uint32_t smem_to_u32(const void* p) {
    uint32_t a;
    asm("{ .reg .u64 t; cvta.to.shared.u64 t, %1; cvt.u32.u64 %0, t; }"
        : "=r"(a) : "l"(p));
    return a;
}
__device__ __forceinline__ void ldm4(uint32_t* r, uint32_t addr) {
    asm volatile("ldmatrix.sync.aligned.m8n8.x4.shared.b16 {%0,%1,%2,%3}, [%4];"
                 : "=r"(r[0]), "=r"(r[1]), "=r"(r[2]), "=r"(r[3]) : "r"(addr));
}
__device__ __forceinline__ void ldm4t(uint32_t* r, uint32_t addr) {
    asm volatile("ldmatrix.sync.aligned.m8n8.x4.trans.shared.b16 {%0,%1,%2,%3}, [%4];"
                 : "=r"(r[0]), "=r"(r[1]), "=r"(r[2]), "=r"(r[3]) : "r"(addr));
}
__device__ __forceinline__ void mma16816(float* c, const uint32_t* a, const uint32_t* b) {
    asm volatile("mma.sync.aligned.m16n8k16.row.col.f32.bf16.bf16.f32 "
                 "{%0,%1,%2,%3}, {%4,%5,%6,%7}, {%8,%9}, {%0,%1,%2,%3};"
                 : "+f"(c[0]), "+f"(c[1]), "+f"(c[2]), "+f"(c[3])
                 : "r"(a[0]), "r"(a[1]), "r"(a[2]), "r"(a[3]),
                   "r"(b[0]), "r"(b[1]));
}
__device__ __forceinline__ uint32_t pk(float lo, float hi) {
    uint32_t r;
    asm("cvt.rn.bf16x2.f32 %0, %1, %2;" : "=r"(r) : "f"(hi), "f"(lo));
    return r;
}
__device__ __forceinline__ void cpa16(uint32_t s, const void* g) {
    asm volatile("cp.async.cg.shared.global [%0], [%1], 16;"
                 :: "r"(s), "l"(__cvta_generic_to_global(g)));
}
#define CP_COMMIT() asm volatile("cp.async.commit_group;" ::: "memory")
#define CP_WAIT0()  asm volatile("cp.async.wait_group 0;" ::: "memory")
#define CP_WAIT1()  asm volatile("cp.async.wait_group 1;" ::: "memory")

// ---------------------------------------------------------------------------
// prep: M^T[c'][c] = sum_d Wq[c,d]*Wk[c',d]  (fp32, split hi/lo), u = Wk*bq
// ---------------------------------------------------------------------------
__global__ __launch_bounds__(256)
void prep_kernel(const float* __restrict__ wq,
                 const float* __restrict__ wk,
                 const float* __restrict__ bq)
{
    __shared__ float wkrow[CC];
    __shared__ float bqs[CC];
    const int cp = blockIdx.x;       // c'
    const int c  = threadIdx.x;      // c
    wkrow[c] = wk[cp * CC + c];      // Wk row c' (coalesced)
    bqs[c]   = bq[c];
    __syncthreads();

    float s = 0.f;
#pragma unroll 8
    for (int d = 0; d < CC; d++)
        s += wq[c * CC + d] * wkrow[d];
    __nv_bfloat16 h = __float2bfloat16(s);
    __nv_bfloat16 l = __float2bfloat16(s - __bfloat162float(h));
    g_mthi[cp * CC + c] = h;
    g_mtlo[cp * CC + c] = l;

    if (cp == 0) {   // u[c] = sum_d Wk[c,d]*bq[d]
        float uu = 0.f;
#pragma unroll 8
        for (int d = 0; d < CC; d++)
            uu += wk[c * CC + d] * bqs[d];
        g_u[c] = uu;
    }
}

// Wv^T hi  (v projection uses hi.hi only)
__global__ __launch_bounds__(256)
void cvt_wv_kernel(const float* __restrict__ wv)
{
    int k = blockIdx.x;          // 0..255
    int n = threadIdx.x;         // 0..255
    g_wvth[n * CC + k] = __float2bfloat16(wv[k * CC + n]);
}

// ---------------------------------------------------------------------------
// cvt_x: x -> bf16 hi/lo, plus c_i = x_i . u  (block = 4 rows of 256)
// ---------------------------------------------------------------------------
__global__ __launch_bounds__(256)
void cvt_x_kernel(const float* __restrict__ x)
{
    __shared__ float red[8];
    const int tid = threadIdx.x;
    size_t i = (size_t)blockIdx.x * 256 + tid;   // float4 index
    float4 v = ((const float4*)x)[i];
    __nv_bfloat16 h0 = __float2bfloat16(v.x);
    __nv_bfloat16 h1 = __float2bfloat16(v.y);
    __nv_bfloat16 h2 = __float2bfloat16(v.z);
    __nv_bfloat16 h3 = __float2bfloat16(v.w);
    __nv_bfloat16 l0 = __float2bfloat16(v.x - __bfloat162float(h0));
    __nv_bfloat16 l1 = __float2bfloat16(v.y - __bfloat162float(h1));
    __nv_bfloat16 l2 = __float2bfloat16(v.z - __bfloat162float(h2));
    __nv_bfloat16 l3 = __float2bfloat16(v.w - __bfloat162float(h3));
    g_xhi[i * 2 + 0] = __halves2bfloat162(h0, h1);
    g_xhi[i * 2 + 1] = __halves2bfloat162(h2, h3);
    g_xlo[i * 2 + 0] = __halves2bfloat162(l0, l1);
    g_xlo[i * 2 + 1] = __halves2bfloat162(l2, l3);

    // c_i = x_i . u  : 64 threads (2 warps) per row
    int col = (tid * 4) & 255;
    float p = v.x * g_u[col] + v.y * g_u[col + 1]
            + v.z * g_u[col + 2] + v.w * g_u[col + 3];
#pragma unroll
    for (int o = 16; o > 0; o >>= 1)
        p += __shfl_xor_sync(0xffffffffu, p, o);
    if ((tid & 31) == 0) red[tid >> 5] = p;
    __syncthreads();
    if (tid < 4)
        g_c[(size_t)blockIdx.x * 4 + tid] = red[2 * tid] + red[2 * tid + 1];
}

// ---------------------------------------------------------------------------
// t/v GEMM via warp-level mma.sync.
// sel 0: t = x * M      (bf16x3), store hi/lo.  sel 1: v = x*Wv + bv (hi only)
// CTA: M=128 x N=128, 8 warps (4 m x 2 n), warp tile 32x64.
// Grid (4, MROWS/128): the 4 (nb,sel) CTAs sharing an A-tile are launch-
// adjacent -> same wave -> A tile read once from DRAM, then 3x from L2.
// Loads are plain LDG+STS (compiler-hoisted, latency hidden by occ=2).
// ---------------------------------------------------------------------------
#define KSTR 72
#define ASZ  (128 * KSTR)              // bf16 elements per tile
#define SM_AH 0
#define SM_AL (ASZ)
#define SM_BH (2 * ASZ)
#define SM_BL (3 * ASZ)
#define QKV_SMEM (4 * ASZ * 2)         // 73728 bytes

__global__ __launch_bounds__(256, 2)
void tv_mma_kernel(const float* __restrict__ bv)
{
    extern __shared__ __align__(128) __nv_bfloat16 smem[];
    const uint32_t sb = smem_to_u32(smem);

    const int tid  = threadIdx.x;
    const int wid  = tid >> 5;
    const int lane = tid & 31;
    const int wm   = wid & 3;          // 0..3  (m)
    const int wn   = wid >> 2;         // 0..1  (n)

    const int m0  = blockIdx.y * 128;
    const int nb  = (blockIdx.x & 1) * 128;
    const int sel = blockIdx.x >> 1;   // 0 = t, 1 = v
    const bool full = (sel == 0);
    __nv_bfloat16* oh = full ? g_th : g_vh;
    __nv_bfloat16* ol = g_tl;
    const __nv_bfloat16* __restrict__ wh = full ? g_mthi : g_wvth;
    const __nv_bfloat16* __restrict__ wl = g_mtlo;
    const __nv_bfloat16* __restrict__ xh = (const __nv_bfloat16*)g_xhi;
    const __nv_bfloat16* __restrict__ xl = (const __nv_bfloat16*)g_xlo;

    float acc[2][8][4];
#pragma unroll
    for (int mt = 0; mt < 2; mt++)
#pragma unroll
        for (int nt = 0; nt < 8; nt++)
#pragma unroll
            for (int j = 0; j < 4; j++) acc[mt][nt][j] = 0.f;

    const int q  = lane >> 3;          // matrix index 0..3
    const int ri = lane & 7;           // row within matrix
    const uint32_t a_row = (uint32_t)((wm * 32 + (q & 1) * 8 + ri) * (KSTR * 2) + (q >> 1) * 16);
    const uint32_t b_row = (uint32_t)((wn * 64 + (q >> 1) * 8 + ri) * (KSTR * 2) + (q & 1) * 16);

    for (int ct = 0; ct < 4; ct++) {
        const int kt = ct * 64;
        __syncthreads();
#pragma unroll
        for (int it = 0; it < 4; it++) {
            int u = tid + it * 256;            // 0..1023
            int r = u >> 3, c = u & 7;
            size_t src = (size_t)(m0 + r) * CC + kt + c * 8;
            uint32_t d = (uint32_t)(r * KSTR + c * 8);
            *(float4*)&smem[SM_AH + d] = *(const float4*)&xh[src];
            if (full) *(float4*)&smem[SM_AL + d] = *(const float4*)&xl[src];
        }
#pragma unroll
        for (int it = 0; it < 4; it++) {
            int u = tid + it * 256;
            int r = u >> 3, c = u & 7;
            size_t src = (size_t)(nb + r) * CC + kt + c * 8;
            uint32_t d = (uint32_t)(r * KSTR + c * 8);
            *(float4*)&smem[SM_BH + d] = *(const float4*)&wh[src];
            if (full) *(float4*)&smem[SM_BL + d] = *(const float4*)&wl[src];
        }
        __syncthreads();

#pragma unroll
        for (int ks = 0; ks < 4; ks++) {
            const uint32_t koff = (uint32_t)(ks * 32);
            uint32_t ah[2][4], ax[2][4], bh[4][4], bx[4][4];
#pragma unroll
            for (int mt = 0; mt < 2; mt++)
                ldm4(ah[mt], sb + SM_AH * 2 + a_row + (uint32_t)(mt * 16 * KSTR * 2) + koff);
#pragma unroll
            for (int np = 0; np < 4; np++)
                ldm4(bh[np], sb + SM_BH * 2 + b_row + (uint32_t)(np * 16 * KSTR * 2) + koff);
#pragma unroll
            for (int mt = 0; mt < 2; mt++)
#pragma unroll
                for (int nt = 0; nt < 8; nt++)
                    mma16816(acc[mt][nt], ah[mt], &bh[nt >> 1][(nt & 1) * 2]);
            if (full) {
#pragma unroll
                for (int np = 0; np < 4; np++)
                    ldm4(bx[np], sb + SM_BL * 2 + b_row + (uint32_t)(np * 16 * KSTR * 2) + koff);
#pragma unroll
                for (int mt = 0; mt < 2; mt++)
#pragma unroll
                    for (int nt = 0; nt < 8; nt++)
                        mma16816(acc[mt][nt], ah[mt], &bx[nt >> 1][(nt & 1) * 2]);
#pragma unroll
                for (int mt = 0; mt < 2; mt++)
                    ldm4(ax[mt], sb + SM_AL * 2 + a_row + (uint32_t)(mt * 16 * KSTR * 2) + koff);
#pragma unroll
                for (int mt = 0; mt < 2; mt++)
#pragma unroll
                    for (int nt = 0; nt < 8; nt++)
                        mma16816(acc[mt][nt], ax[mt], &bh[nt >> 1][(nt & 1) * 2]);
            }
        }
    }

    // epilogue
    const int g = lane >> 2;
    const int t = lane & 3;
#pragma unroll
    for (int mt = 0; mt < 2; mt++) {
        int row = m0 + wm * 32 + mt * 16 + g;
#pragma unroll
        for (int nt = 0; nt < 8; nt++) {
            int col = nb + wn * 64 + nt * 8 + 2 * t;
            float2 bb = full ? make_float2(0.f, 0.f) : *(const float2*)&bv[col];
#pragma unroll
            for (int h = 0; h < 2; h++) {
                float a = acc[mt][nt][2 * h]     + bb.x;
                float b = acc[mt][nt][2 * h + 1] + bb.y;
                size_t off = (size_t)(row + 8 * h) * CC + col;
                __nv_bfloat16 ha = __float2bfloat16(a);
                __nv_bfloat16 hb = __float2bfloat16(b);
                *(__nv_bfloat162*)&oh[off] = __halves2bfloat162(ha, hb);
                if (full) {
                    __nv_bfloat16 la = __float2bfloat16(a - __bfloat162float(ha));
                    __nv_bfloat16 lb = __float2bfloat16(b - __bfloat162float(hb));
                    *(__nv_bfloat162*)&ol[off] = __halves2bfloat162(la, lb);
                }
            }
        }
    }
}

// ---------------------------------------------------------------------------
// Attention via mma.sync per (b,h) slice, flash-style register softmax.
// S = t x^T (bf16x3) + c_j; softmax via quad shfl; P from S fragments;
// O = P * V_hi, single pass over c, V double-buffered via cp.async.
// (round-14 structure: fp32 xin residual read at epilogue)
// ---------------------------------------------------------------------------
#define AT_STR 264                      // bf16 row stride (528B: conflict-free)
#define QH_E 0
#define QL_E 33792                      // 128*264
#define T0_E 67584                      // K hi  / V buf0  (64*264 elts)
#define T1_E 84480                      // K lo  / V buf1
#define AT_SMEM ((T1_E + 64 * AT_STR) * 2)   // 202752 bytes
#define AT_SMEM_TOT (AT_SMEM + 1024)         // + c_j slice (256 floats)

__global__ __launch_bounds__(256, 1)
void attn_mma_kernel(const float* __restrict__ xin,
                     const float* __restrict__ gamma,
                     float* __restrict__ out)
{
    extern __shared__ __align__(128) __nv_bfloat16 sm[];
    const uint32_t sb = smem_to_u32(sm);
    float* csm = (float*)((char*)sm + AT_SMEM);

    const int bh = blockIdx.x;
    const size_t base = (size_t)bh * WW * CC;
    const int tid  = threadIdx.x;
    const int wid  = tid >> 5;
    const int lane = tid & 31;
    const int g  = lane >> 2, t  = lane & 3;
    const int qm = lane >> 3, ri = lane & 7;

    csm[tid] = g_c[(size_t)bh * WW + tid];   // softmax column bias slice

    // ldmatrix per-lane addresses
    const uint32_t a_hi = sb +
        (uint32_t)(((wid * 16 + (qm & 1) * 8 + ri) * AT_STR + (qm >> 1) * 8) * 2);
    const uint32_t a_lo = a_hi + QL_E * 2;
    const uint32_t bk_off = (uint32_t)((((qm >> 1) * 8 + ri) * AT_STR + (qm & 1) * 8) * 2);
    const uint32_t bv_off = (uint32_t)((((qm & 1) * 8 + ri) * AT_STR + (qm >> 1) * 8) * 2);
    const uint32_t buf0 = sb + T0_E * 2;
    const uint32_t buf1 = sb + T1_E * 2;

    for (int qb = 0; qb < 2; qb++) {
        __syncthreads();   // previous iteration fully done with T buffers

        // ---- async-load T block hi/lo (128 x 256) : Q-role ----
        {
            const __nv_bfloat16* qh = g_th + base + (size_t)qb * 128 * CC;
            const __nv_bfloat16* ql = g_tl + base + (size_t)qb * 128 * CC;
#pragma unroll
            for (int it = 0; it < 16; it++) {
                int u = tid + it * 256;
                int r = u >> 5, c8 = u & 31;
                uint32_t d = (uint32_t)((r * AT_STR + c8 * 8) * 2);
                cpa16(sb + QH_E * 2 + d, qh + r * CC + c8 * 8);
                cpa16(sb + QL_E * 2 + d, ql + r * CC + c8 * 8);
            }
            CP_COMMIT();
        }
        // ---- async-load x tile 0 (hi->buf0, lo->buf1) : K-role ----
        {
            const __nv_bfloat16* kh = (const __nv_bfloat16*)g_xhi + base;
            const __nv_bfloat16* kl = (const __nv_bfloat16*)g_xlo + base;
#pragma unroll
            for (int it = 0; it < 8; it++) {
                int u = tid + it * 256;
                int r = u >> 5, c8 = u & 31;
                uint32_t d = (uint32_t)((r * AT_STR + c8 * 8) * 2);
                cpa16(buf0 + d, kh + r * CC + c8 * 8);
                cpa16(buf1 + d, kl + r * CC + c8 * 8);
            }
            CP_COMMIT();
        }

        // ---- S = T x^T (per warp: 16 rows x 256 keys), bf16x3 ----
        float sacc[32][4];
#pragma unroll
        for (int nt = 0; nt < 32; nt++)
#pragma unroll
            for (int j = 0; j < 4; j++) sacc[nt][j] = 0.f;

        for (int kt = 0; kt < 4; kt++) {
            CP_WAIT0();
            __syncthreads();

#pragma unroll 2
            for (int kc = 0; kc < 16; kc++) {
                uint32_t ah[4], al[4];
                ldm4(ah, a_hi + kc * 32);
                ldm4(al, a_lo + kc * 32);
#pragma unroll
                for (int jg = 0; jg < 4; jg++) {
                    uint32_t bh4[4], bl4[4];
                    uint32_t roff = bk_off + (uint32_t)(jg * 16 * AT_STR * 2) + kc * 32;
                    ldm4(bh4, buf0 + roff);
                    ldm4(bl4, buf1 + roff);
                    float* s0 = sacc[kt * 8 + jg * 2];
                    float* s1 = sacc[kt * 8 + jg * 2 + 1];
                    mma16816(s0, ah, bh4 + 0); mma16816(s1, ah, bh4 + 2);
                    mma16816(s0, ah, bl4 + 0); mma16816(s1, ah, bl4 + 2);
                    mma16816(s0, al, bh4 + 0); mma16816(s1, al, bh4 + 2);
                }
            }
            __syncthreads();
            if (kt < 3) {   // stream next x tile
                const __nv_bfloat16* kh = (const __nv_bfloat16*)g_xhi + base + (size_t)(kt + 1) * 64 * CC;
                const __nv_bfloat16* kl = (const __nv_bfloat16*)g_xlo + base + (size_t)(kt + 1) * 64 * CC;
#pragma unroll
                for (int it = 0; it < 8; it++) {
                    int u = tid + it * 256;
                    int r = u >> 5, c8 = u & 31;
                    uint32_t d = (uint32_t)((r * AT_STR + c8 * 8) * 2);
                    cpa16(buf0 + d, kh + r * CC + c8 * 8);
                    cpa16(buf1 + d, kl + r * CC + c8 * 8);
                }
                CP_COMMIT();
            }
        }

        // ---- prefetch V tile 0 into buf0 (overlaps softmax) ----
        {
            const __nv_bfloat16* vh = g_vh + base;
#pragma unroll
            for (int it = 0; it < 8; it++) {
                int u = tid + it * 256;
                int r = u >> 5, c8 = u & 31;
                cpa16(buf0 + (uint32_t)((r * AT_STR + c8 * 8) * 2), vh + r * CC + c8 * 8);
            }
            CP_COMMIT();
        }

        // ---- add softmax column bias c_j ----
#pragma unroll
        for (int nt = 0; nt < 32; nt++) {
            float c0 = csm[nt * 8 + 2 * t];
            float c1 = csm[nt * 8 + 2 * t + 1];
            sacc[nt][0] += c0; sacc[nt][1] += c1;
            sacc[nt][2] += c0; sacc[nt][3] += c1;
        }

        // ---- softmax (warp-local; rows g and g+8 per thread-quad) ----
        float mx0 = -1e30f, mx1 = -1e30f;
#pragma unroll
        for (int nt = 0; nt < 32; nt++) {
            mx0 = fmaxf(mx0, fmaxf(sacc[nt][0], sacc[nt][1]));
            mx1 = fmaxf(mx1, fmaxf(sacc[nt][2], sacc[nt][3]));
        }
        mx0 = fmaxf(mx0, __shfl_xor_sync(0xffffffffu, mx0, 1));
        mx0 = fmaxf(mx0, __shfl_xor_sync(0xffffffffu, mx0, 2));
        mx1 = fmaxf(mx1, __shfl_xor_sync(0xffffffffu, mx1, 1));
        mx1 = fmaxf(mx1, __shfl_xor_sync(0xffffffffu, mx1, 2));
        float sm0 = 0.f, sm1 = 0.f;
#pragma unroll
        for (int nt = 0; nt < 32; nt++) {
            sacc[nt][0] = __expf(sacc[nt][0] - mx0);
            sacc[nt][1] = __expf(sacc[nt][1] - mx0);
            sacc[nt][2] = __expf(sacc[nt][2] - mx1);
            sacc[nt][3] = __expf(sacc[nt][3] - mx1);
            sm0 += sacc[nt][0] + sacc[nt][1];
            sm1 += sacc[nt][2] + sacc[nt][3];
        }
        sm0 += __shfl_xor_sync(0xffffffffu, sm0, 1);
        sm0 += __shfl_xor_sync(0xffffffffu, sm0, 2);
        sm1 += __shfl_xor_sync(0xffffffffu, sm1, 1);
        sm1 += __shfl_xor_sync(0xffffffffu, sm1, 2);
        const float inv0 = 1.f / sm0, inv1 = 1.f / sm1;

        // ---- pack P fragments straight from S accumulators ----
        uint32_t phi[16][4];
#pragma unroll
        for (int m = 0; m < 16; m++) {
            phi[m][0] = pk(sacc[2 * m][0] * inv0,     sacc[2 * m][1] * inv0);
            phi[m][1] = pk(sacc[2 * m][2] * inv1,     sacc[2 * m][3] * inv1);
            phi[m][2] = pk(sacc[2 * m + 1][0] * inv0, sacc[2 * m + 1][1] * inv0);
            phi[m][3] = pk(sacc[2 * m + 1][2] * inv1, sacc[2 * m + 1][3] * inv1);
        }

        // ---- O = P V_hi, single pass, V double-buffered ----
        float oacc[32][4];
#pragma unroll
        for (int nt = 0; nt < 32; nt++)
#pragma unroll
            for (int j = 0; j < 4; j++) oacc[nt][j] = 0.f;

        for (int vt = 0; vt < 4; vt++) {
            if (vt < 3) {   // prefetch next V tile into the other buffer
                const __nv_bfloat16* vh = g_vh + base + (size_t)(vt + 1) * 64 * CC;
                uint32_t nbuf = ((vt + 1) & 1) ? buf1 : buf0;
#pragma unroll
                for (int it = 0; it < 8; it++) {
                    int u = tid + it * 256;
                    int r = u >> 5, c8 = u & 31;
                    cpa16(nbuf + (uint32_t)((r * AT_STR + c8 * 8) * 2), vh + r * CC + c8 * 8);
                }
                CP_COMMIT();
                CP_WAIT1();
            } else {
                CP_WAIT0();
            }
            __syncthreads();

            const uint32_t cbuf = (vt & 1) ? buf1 : buf0;
#pragma unroll
            for (int ml = 0; ml < 4; ml++) {
                const uint32_t* p = phi[vt * 4 + ml];
#pragma unroll
                for (int cg = 0; cg < 16; cg++) {
                    uint32_t bh4[4];
                    ldm4t(bh4, cbuf + bv_off + (uint32_t)(ml * 16 * AT_STR * 2) + cg * 32);
                    mma16816(oacc[cg * 2],     p, bh4 + 0);
                    mma16816(oacc[cg * 2 + 1], p, bh4 + 2);
                }
            }
            __syncthreads();
        }

        // ---- epilogue: out = gamma * O + x ----
#pragma unroll
        for (int nt = 0; nt < 32; nt++) {
            int c = nt * 8 + 2 * t;
            float2 gm = *(const float2*)&gamma[c];
            int r0 = qb * 128 + wid * 16 + g;
            size_t o0 = base + (size_t)r0 * CC + c;
            size_t o1 = o0 + (size_t)8 * CC;
            float2 x0 = *(const float2*)&xin[o0];
            float2 x1 = *(const float2*)&xin[o1];
            float2 w0, w1;
            w0.x = gm.x * oacc[nt][0] + x0.x;
            w0.y = gm.y * oacc[nt][1] + x0.y;
            w1.x = gm.x * oacc[nt][2] + x1.x;
            w1.y = gm.y * oacc[nt][3] + x1.y;
            *(float2*)&out[o0] = w0;
            *(float2*)&out[o1] = w1;
        }
    }
}

// ---------------------------------------------------------------------------
extern "C" void kernel_launch(void* const* d_in, const int* in_sizes, int n_in,
                              void* d_out, int out_size)
{
    const float* x     = (const float*)d_in[0];
    const float* wq    = (const float*)d_in[1];
    const float* bq    = (const float*)d_in[2];
    const float* wk    = (const float*)d_in[3];
    const float* wv    = (const float*)d_in[5];
    const float* bv    = (const float*)d_in[6];
    const float* gamma = (const float*)d_in[7];
    float* out = (float*)d_out;

    cudaFuncSetAttribute(tv_mma_kernel,
                         cudaFuncAttributeMaxDynamicSharedMemorySize, QKV_SMEM);
    cudaFuncSetAttribute(attn_mma_kernel,
                         cudaFuncAttributeMaxDynamicSharedMemorySize, AT_SMEM_TOT);

    // 1) M = Wq Wk^T (hi/lo), u = Wk bq ; Wv^T hi
    prep_kernel<<<CC, CC>>>(wq, wk, bq);
    cvt_wv_kernel<<<CC, CC>>>(wv);

    // 2) x -> bf16 hi/lo + c_i = x_i . u   (needs g_u from prep)
    cvt_x_kernel<<<(MROWS * CC / 4) / 256, 256>>>(x);

    // 3) t = x M (bf16x3, hi/lo out); v = x Wv + bv (hi out)
    tv_mma_kernel<<<dim3(4, MROWS / 128), 256, QKV_SMEM>>>(bv);

    // 4) attention + residual via warp-mma, cp.async pipelined
    attn_mma_kernel<<<NBH, 256, AT_SMEM_TOT>>>(x, gamma, out);
}